// round 6
// baseline (speedup 1.0000x reference)
#include <cuda_runtime.h>
#include <cstdint>
#include <cstddef>

// ---------------- problem constants ----------------
#define FF   128
#define EE   128
#define VV   4
#define BB   2
#define NHh  7
#define PFp  32768
#define P5p  8192
#define P4p  2048
#define N6n  196608
#define N5n  49152
#define N4n  12288
#define TP   128
#define SA   132
#define NT   1024

#define BAR_SYNC(id, cnt)   asm volatile("bar.sync %0, %1;\n"   :: "r"(id), "r"(cnt) : "memory")
#define BAR_ARRIVE(id, cnt) asm volatile("bar.arrive %0, %1;\n" :: "r"(id), "r"(cnt) : "memory")

typedef unsigned long long u64;

__device__ __forceinline__ unsigned f2tf32(float x) {
    unsigned y;
    asm("cvt.rna.tf32.f32 %0, %1;" : "=r"(y) : "f"(x));
    return y;
}

__device__ __forceinline__ u64 fma2(u64 a, u64 b, u64 c) {
    u64 d;
    asm("fma.rn.f32x2 %0, %1, %2, %3;" : "=l"(d) : "l"(a), "l"(b), "l"(c));
    return d;
}
__device__ __forceinline__ u64 add2(u64 a, u64 b) {
    u64 d;
    asm("add.rn.f32x2 %0, %1, %2;" : "=l"(d) : "l"(a), "l"(b));
    return d;
}

__device__ __forceinline__ void mma_tf32(float c[4],
                                         unsigned a0, unsigned a1, unsigned a2, unsigned a3,
                                         unsigned b0, unsigned b1) {
    asm volatile(
        "mma.sync.aligned.m16n8k8.row.col.f32.tf32.tf32.f32 "
        "{%0,%1,%2,%3}, {%4,%5,%6,%7}, {%8,%9}, {%0,%1,%2,%3};\n"
        : "+f"(c[0]), "+f"(c[1]), "+f"(c[2]), "+f"(c[3])
        : "r"(a0), "r"(a1), "r"(a2), "r"(a3), "r"(b0), "r"(b1));
}

__device__ __forceinline__ void cp16(unsigned dst, const void* src) {
    asm volatile("cp.async.cg.shared.global [%0], [%1], 16;\n" :: "r"(dst), "l"(src) : "memory");
}

// 512 mma-group threads, 8 chunks each = 128 rows x 32 x 16B
__device__ __forceinline__ void issue_gather(const float* tb, const int* sIdx,
                                             unsigned aBase, int mtid) {
    #pragma unroll
    for (int j = 0; j < 8; j++) {
        int c = mtid + j * 512;
        int r = c >> 5, s = c & 31;
        cp16(aBase + (unsigned)(r * SA + s * 4) * 4u,
             tb + (size_t)sIdx[r] * FF + s * 4);
    }
    asm volatile("cp.async.commit_group;\n" ::: "memory");
}

// ===================== fused, warp-specialized, 32 warps =====================
// warps  0-15: gather table6 (cp.async) + tf32 mma (strip x n-half) -> res smem
// warps 16-31: e5/e4 interpolation (pc4 x col-half), consume res, write out
__global__ __launch_bounds__(NT, 1)
void fused_kernel(const float* __restrict__ t6, const float* __restrict__ t5,
                  const float* __restrict__ t4, const float* __restrict__ W,
                  const float* __restrict__ bias,
                  const float* __restrict__ rd5, const float* __restrict__ rd4,
                  const float* __restrict__ m5,  const float* __restrict__ m4,
                  const int* __restrict__ var_idx, const int* __restrict__ idx6,
                  const int* __restrict__ nh5, const int* __restrict__ nh4,
                  float* __restrict__ out)
{
    extern __shared__ unsigned sm[];
    unsigned* sWf  = sm;                               // 16384 words
    unsigned* sA   = sm + 16384;                       // 2 x [128][SA]
    float*    sB   = (float*)(sm + 16384 + 2 * TP * SA);
    int*      sIdx = (int*)(sB + EE);                  // [128]
    int*      sN4  = sIdx + TP;                        // [56]
    int*      sN5  = sN4 + 56;                         // [224]
    float*    wtab = (float*)(sN5 + 224);              // 8 pc4 x [16 o16][8 n] float4

    const int b    = blockIdx.y;
    const int p0   = blockIdx.x * TP;
    const int tid  = threadIdx.x;
    const int warp = tid >> 5, lane = tid & 31;

    if (warp < 16) {
        // ================= MMA group (threads 0..511) =================
        const int mtid  = tid;
        const int strip = warp >> 1;                   // 0..7 -> M16 strip
        const int h     = warp & 1;                    // n-half
        const int g = lane >> 2, t = lane & 3;
        const int m0 = strip * 16;

        if (mtid < TP) sIdx[mtid] = idx6[b * PFp + p0 + mtid];
        if (mtid < EE) sB[mtid]   = bias[mtid];
        BAR_SYNC(5, 512);

        issue_gather(t6 + (size_t)var_idx[b * VV + 0] * N6n * FF, sIdx,
                     (unsigned)__cvta_generic_to_shared(sA), mtid);
        issue_gather(t6 + (size_t)var_idx[b * VV + 1] * N6n * FF, sIdx,
                     (unsigned)__cvta_generic_to_shared(sA + TP * SA), mtid);

        // W in mma-fragment order (tf32, rna)
        for (int fi = mtid; fi < 8192; fi += 512) {
            int kt = fi >> 9, nt = (fi >> 5) & 15, ln = fi & 31;
            int gg = ln >> 2, tt = ln & 3;
            int k0 = kt * 8 + tt, n = nt * 8 + gg;
            sWf[fi * 2 + 0] = f2tf32(W[(size_t)k0 * EE + n]);
            sWf[fi * 2 + 1] = f2tf32(W[(size_t)(k0 + 4) * EE + n]);
        }

        for (int v = 0; v < VV; v++) {
            if (v == 0) { asm volatile("cp.async.wait_group 1;\n" ::: "memory"); }
            else        { asm volatile("cp.async.wait_group 0;\n" ::: "memory"); }
            BAR_SYNC(5, 512);   // gathers (and W, v=0) visible to whole group

            const unsigned* A = sA + (v & 1) * TP * SA;
            float acc[8][4];
            #pragma unroll
            for (int nt = 0; nt < 8; nt++) {
                acc[nt][0] = 0.f; acc[nt][1] = 0.f; acc[nt][2] = 0.f; acc[nt][3] = 0.f;
            }
            #pragma unroll 4
            for (int kt = 0; kt < 16; kt++) {
                const int kb = kt * 8;
                unsigned a0 = A[(m0 + g    ) * SA + kb + t];
                unsigned a1 = A[(m0 + g + 8) * SA + kb + t];
                unsigned a2 = A[(m0 + g    ) * SA + kb + t + 4];
                unsigned a3 = A[(m0 + g + 8) * SA + kb + t + 4];
                const uint2* wrow = (const uint2*)sWf + kt * 512 + h * 256 + lane;
                #pragma unroll
                for (int nt = 0; nt < 8; nt++) {
                    uint2 bb = wrow[nt * 32];
                    mma_tf32(acc[nt], a0, a1, a2, a3, bb.x, bb.y);
                }
            }

            // both half-warps of the strip done reading A rows before overwrite
            BAR_SYNC(8 + strip, 64);

            float* res = (float*)A;
            #pragma unroll
            for (int nt = 0; nt < 8; nt++) {
                int col = (h * 8 + nt) * 8 + 2 * t;
                float b0 = sB[col], b1 = sB[col + 1];
                *(float2*)(res + (m0 + g    ) * SA + col) =
                    make_float2(acc[nt][0] + b0, acc[nt][1] + b1);
                *(float2*)(res + (m0 + g + 8) * SA + col) =
                    make_float2(acc[nt][2] + b0, acc[nt][3] + b1);
            }
            BAR_ARRIVE(1 + (v & 1), NT);                // FULL_v

            if (v >= 1 && v + 1 < VV) {
                BAR_SYNC(3 + ((v - 1) & 1), NT);        // FREE_{v-1}
                issue_gather(t6 + (size_t)var_idx[b * VV + v + 1] * N6n * FF, sIdx,
                             (unsigned)__cvta_generic_to_shared(sA + ((v + 1) & 1) * TP * SA),
                             mtid);
            }
        }
    } else {
        // ================= INTERP group (threads 512..1023) =================
        const int itid = tid - 512;
        const int iw   = warp - 16;
        const int q    = iw >> 1;                       // pc4 within tile (0..7)
        const int h    = iw & 1;                        // col-half
        const int pc4  = (p0 >> 4) + q;

        if (itid < 56) {
            int pp = itid / 7, nn = itid - pp * 7;
            sN4[itid] = nh4[((size_t)(b * P4p) + (p0 >> 4) + pp) * NHh + nn];
        }
        if (itid < 224) {
            int pp = itid / 7, nn = itid - pp * 7;
            sN5[itid] = nh5[((size_t)(b * P5p) + (p0 >> 2) + pp) * NHh + nn];
        }

        // per-lane weights -> packed smem table (h==0 warp of each pc4 only)
        float* wt = wtab + q * 512;
        if (h == 0) {
            float w[NHh];
            const float* rdp; const float* mkp;
            if (lane < 16) {
                rdp = rd4 + ((size_t)(b * P4p + pc4) * 16 + lane) * NHh;
                mkp = m4  +  (size_t)(b * P4p + pc4) * NHh;
            } else {
                int g5 = lane - 16, s5 = g5 >> 2, o5 = g5 & 3;
                int pc5 = pc4 * 4 + s5;
                rdp = rd5 + ((size_t)(b * P5p + pc5) * 4 + o5) * NHh;
                mkp = m5  +  (size_t)(b * P5p + pc5) * NHh;
            }
            float ss = 0.f;
            #pragma unroll
            for (int n = 0; n < NHh; n++) {
                float x  = rdp[n] + mkp[n] * 1e10f;
                float wi = 1.0f / (1e-20f + x);
                w[n] = wi; ss += wi;
            }
            float inv = 1.0f / ss;
            #pragma unroll
            for (int n = 0; n < NHh; n++) w[n] *= inv;

            const int o = lane & 15;
            float2* dst = (float2*)(wt + o * 32) + (lane < 16 ? 0 : 1);
            #pragma unroll
            for (int n = 0; n < NHh; n++)
                dst[n * 2] = make_float2(w[n], w[n]);
        }
        BAR_SYNC(7, 512);                               // sN4/sN5/wtab ready

        const ulonglong2* wt2 = (const ulonglong2*)wt;  // [o16*8 + n]
        const int coff = h * 32 + lane;                 // u64 column offset in a row

        for (int v = 0; v < VV; v++) {
            const int tv = var_idx[b * VV + v];
            const u64* tb4 = (const u64*)(t4 + (size_t)tv * N4n * FF);
            const u64* tb5 = (const u64*)(t5 + (size_t)tv * N5n * FF);
            const float* res = (const float*)(sA + (v & 1) * TP * SA);
            float* op = out + ((size_t)(b * VV + v) * PFp + p0 + q * 16) * EE;

            u64 f4[NHh], fA[NHh], fB[NHh];
            #pragma unroll
            for (int n = 0; n < NHh; n++)
                f4[n] = tb4[(size_t)sN4[q * 7 + n] * 64 + coff];
            #pragma unroll
            for (int n = 0; n < NHh; n++)
                fA[n] = tb5[(size_t)sN5[(q * 4 + 0) * 7 + n] * 64 + coff];

            BAR_SYNC(1 + (v & 1), NT);                  // FULL_v

            auto doS5 = [&](int s5, const u64* f5) {
                #pragma unroll
                for (int o5 = 0; o5 < 4; o5++) {
                    const int o16 = s5 * 4 + o5;
                    u64 a = *(const u64*)(res + (q * 16 + o16) * SA + 2 * coff);
                    u64 p = 0;
                    #pragma unroll
                    for (int n = 0; n < NHh; n++) {
                        ulonglong2 wv = wt2[o16 * 8 + n];   // (w4w4, w5w5)
                        a = fma2(wv.x, f4[n], a);
                        p = fma2(wv.y, f5[n], p);
                    }
                    a = add2(a, p);
                    *(u64*)(op + (size_t)o16 * EE + 2 * coff) = a;
                }
            };

            #pragma unroll
            for (int n = 0; n < NHh; n++)
                fB[n] = tb5[(size_t)sN5[(q * 4 + 1) * 7 + n] * 64 + coff];
            doS5(0, fA);
            #pragma unroll
            for (int n = 0; n < NHh; n++)
                fA[n] = tb5[(size_t)sN5[(q * 4 + 2) * 7 + n] * 64 + coff];
            doS5(1, fB);
            #pragma unroll
            for (int n = 0; n < NHh; n++)
                fB[n] = tb5[(size_t)sN5[(q * 4 + 3) * 7 + n] * 64 + coff];
            doS5(2, fA);
            doS5(3, fB);

            BAR_ARRIVE(3 + (v & 1), NT);                // FREE_v
        }
    }
}

// ===================== launch =====================
extern "C" void kernel_launch(void* const* d_in, const int* in_sizes, int n_in,
                              void* d_out, int out_size)
{
    const float* table6  = (const float*)d_in[0];
    const float* table5  = (const float*)d_in[1];
    const float* table4  = (const float*)d_in[2];
    const float* W       = (const float*)d_in[3];
    const float* bias    = (const float*)d_in[4];
    const float* rd5     = (const float*)d_in[5];
    const float* rd4     = (const float*)d_in[6];
    const float* m5      = (const float*)d_in[7];
    const float* m4      = (const float*)d_in[8];
    const int*   var_idx = (const int*)d_in[9];
    const int*   idx6    = (const int*)d_in[10];
    const int*   nh5     = (const int*)d_in[11];
    const int*   nh4     = (const int*)d_in[12];
    float* out = (float*)d_out;

    const int smem = (16384 + 2 * TP * SA + EE + TP + 56 + 224 + 4096) * 4;  // 219,232 B
    cudaFuncSetAttribute(fused_kernel, cudaFuncAttributeMaxDynamicSharedMemorySize, smem);

    dim3 grid(PFp / TP, BB);   // 512 CTAs
    fused_kernel<<<grid, NT, smem>>>(table6, table5, table4, W, bias,
                                     rd5, rd4, m5, m4,
                                     var_idx, idx6, nh5, nh4, out);
}

// round 7
// speedup vs baseline: 1.4978x; 1.4978x over previous
#include <cuda_runtime.h>
#include <cstdint>
#include <cstddef>

// ---------------- problem constants ----------------
#define FF   128
#define EE   128
#define VV   4
#define BB   2
#define NHh  7
#define PFp  32768
#define P5p  8192
#define P4p  2048
#define N6n  196608
#define N5n  49152
#define N4n  12288
#define TP   128
#define SA   132
#define NT   512

#define BAR_SYNC(id, cnt)   asm volatile("bar.sync %0, %1;\n"   :: "r"(id), "r"(cnt) : "memory")
#define BAR_ARRIVE(id, cnt) asm volatile("bar.arrive %0, %1;\n" :: "r"(id), "r"(cnt) : "memory")

typedef unsigned long long u64;

__device__ __forceinline__ unsigned f2tf32(float x) {
    unsigned y;
    asm("cvt.rna.tf32.f32 %0, %1;" : "=r"(y) : "f"(x));
    return y;
}

__device__ __forceinline__ u64 fma2(u64 a, u64 b, u64 c) {
    u64 d;
    asm("fma.rn.f32x2 %0, %1, %2, %3;" : "=l"(d) : "l"(a), "l"(b), "l"(c));
    return d;
}
__device__ __forceinline__ u64 add2(u64 a, u64 b) {
    u64 d;
    asm("add.rn.f32x2 %0, %1, %2;" : "=l"(d) : "l"(a), "l"(b));
    return d;
}

__device__ __forceinline__ void mma_tf32(float c[4],
                                         unsigned a0, unsigned a1, unsigned a2, unsigned a3,
                                         unsigned b0, unsigned b1) {
    asm volatile(
        "mma.sync.aligned.m16n8k8.row.col.f32.tf32.tf32.f32 "
        "{%0,%1,%2,%3}, {%4,%5,%6,%7}, {%8,%9}, {%0,%1,%2,%3};\n"
        : "+f"(c[0]), "+f"(c[1]), "+f"(c[2]), "+f"(c[3])
        : "r"(a0), "r"(a1), "r"(a2), "r"(a3), "r"(b0), "r"(b1));
}

__device__ __forceinline__ void mbar_wait(unsigned mbar, unsigned parity) {
    asm volatile(
        "{\n\t"
        ".reg .pred P1;\n\t"
        "WAIT_LOOP_%=:\n\t"
        "mbarrier.try_wait.parity.shared.b64 P1, [%0], %1, 0x989680;\n\t"
        "@P1 bra.uni WAIT_DONE_%=;\n\t"
        "bra.uni WAIT_LOOP_%=;\n\t"
        "WAIT_DONE_%=:\n\t"
        "}"
        :: "r"(mbar), "r"(parity) : "memory");
}

// warp 0 of mma group issues 128 row-gathers as 512B bulk copies
__device__ __forceinline__ void issue_bulk_gather(const float* tb, const int* sIdx,
                                                  unsigned dstBase, unsigned mbar, int lane) {
    if (lane == 0) {
        unsigned tx = TP * FF * 4;   // 65536
        asm volatile("mbarrier.arrive.expect_tx.shared.b64 _, [%0], %1;\n"
                     :: "r"(mbar), "r"(tx) : "memory");
    }
    __syncwarp();
    #pragma unroll
    for (int j = 0; j < 4; j++) {
        int r = lane * 4 + j;
        asm volatile(
            "cp.async.bulk.shared::cta.global.mbarrier::complete_tx::bytes "
            "[%0], [%1], 512, [%2];\n"
            :: "r"(dstBase + (unsigned)(r * SA * 4)),
               "l"(tb + (size_t)sIdx[r] * FF), "r"(mbar) : "memory");
    }
}

// ===================== fused, warp-specialized =====================
// warps 0-7:  bulk-gather table6 + tf32 mma (strip-pair x n-half) -> res smem
// warps 8-15: e5/e4 interpolation, consume res, write out
__global__ __launch_bounds__(NT, 1)
void fused_kernel(const float* __restrict__ t6, const float* __restrict__ t5,
                  const float* __restrict__ t4, const float* __restrict__ W,
                  const float* __restrict__ bias,
                  const float* __restrict__ rd5, const float* __restrict__ rd4,
                  const float* __restrict__ m5,  const float* __restrict__ m4,
                  const int* __restrict__ var_idx, const int* __restrict__ idx6,
                  const int* __restrict__ nh5, const int* __restrict__ nh4,
                  float* __restrict__ out)
{
    extern __shared__ unsigned sm[];
    unsigned* sWf  = sm;                               // 16384 words
    unsigned* sA   = sm + 16384;                       // 2 x [128][SA]
    float*    sB   = (float*)(sm + 16384 + 2 * TP * SA);
    int*      sIdx = (int*)(sB + EE);                  // [128]
    int*      sN4  = sIdx + TP;                        // [56]
    int*      sN5  = sN4 + 56;                         // [224]
    unsigned* sMb  = (unsigned*)(sN5 + 224);           // 2 x u64 mbarrier (+pad 4w)
    float*    wtab = (float*)(sMb + 8);                // 8 pc4 x [16][8] float4

    const int b    = blockIdx.y;
    const int p0   = blockIdx.x * TP;
    const int tid  = threadIdx.x;
    const int warp = tid >> 5, lane = tid & 31;

    if (warp < 8) {
        // ================= MMA group (threads 0..255) =================
        const int mtid = tid;
        const int sp = warp >> 1;                      // strip pair 0..3 (M32)
        const int h  = warp & 1;                       // n-half
        const int g = lane >> 2, t = lane & 3;
        const int m0 = sp * 32;

        if (mtid < TP) sIdx[mtid] = idx6[b * PFp + p0 + mtid];
        if (mtid < EE) sB[mtid]   = bias[mtid];
        if (mtid < 2) {
            unsigned mb = (unsigned)__cvta_generic_to_shared(sMb) + mtid * 8;
            asm volatile("mbarrier.init.shared.b64 [%0], 1;\n" :: "r"(mb) : "memory");
        }
        BAR_SYNC(5, 256);                               // sIdx + mbarriers ready

        const unsigned mb0 = (unsigned)__cvta_generic_to_shared(sMb);
        const unsigned aB0 = (unsigned)__cvta_generic_to_shared(sA);

        if (warp == 0) {   // prefetch v=0 (buf0) and v=1 (buf1)
            issue_bulk_gather(t6 + (size_t)var_idx[b * VV + 0] * N6n * FF, sIdx,
                              aB0, mb0, lane);
            issue_bulk_gather(t6 + (size_t)var_idx[b * VV + 1] * N6n * FF, sIdx,
                              aB0 + TP * SA * 4, mb0 + 8, lane);
        }

        // W in mma-fragment order (tf32, rna)
        for (int fi = mtid; fi < 8192; fi += 256) {
            int kt = fi >> 9, nt = (fi >> 5) & 15, ln = fi & 31;
            int gg = ln >> 2, tt = ln & 3;
            int k0 = kt * 8 + tt, n = nt * 8 + gg;
            sWf[fi * 2 + 0] = f2tf32(W[(size_t)k0 * EE + n]);
            sWf[fi * 2 + 1] = f2tf32(W[(size_t)(k0 + 4) * EE + n]);
        }
        BAR_SYNC(5, 256);                               // sWf ready

        for (int v = 0; v < VV; v++) {
            mbar_wait(mb0 + (v & 1) * 8, (v >> 1) & 1); // buffer v&1 full

            const unsigned* A = sA + (v & 1) * TP * SA;
            float acc[2][8][4];
            #pragma unroll
            for (int s = 0; s < 2; s++)
                #pragma unroll
                for (int nt = 0; nt < 8; nt++) {
                    acc[s][nt][0] = 0.f; acc[s][nt][1] = 0.f;
                    acc[s][nt][2] = 0.f; acc[s][nt][3] = 0.f;
                }
            #pragma unroll 4
            for (int kt = 0; kt < 16; kt++) {
                const int kb = kt * 8;
                unsigned a0 = A[(m0 + g     ) * SA + kb + t];
                unsigned a1 = A[(m0 + g +  8) * SA + kb + t];
                unsigned a2 = A[(m0 + g     ) * SA + kb + t + 4];
                unsigned a3 = A[(m0 + g +  8) * SA + kb + t + 4];
                unsigned c0 = A[(m0 + g + 16) * SA + kb + t];
                unsigned c1 = A[(m0 + g + 24) * SA + kb + t];
                unsigned c2 = A[(m0 + g + 16) * SA + kb + t + 4];
                unsigned c3 = A[(m0 + g + 24) * SA + kb + t + 4];
                const uint2* wrow = (const uint2*)sWf + kt * 512 + h * 256 + lane;
                #pragma unroll
                for (int nt = 0; nt < 8; nt++) {
                    uint2 bb = wrow[nt * 32];
                    mma_tf32(acc[0][nt], a0, a1, a2, a3, bb.x, bb.y);
                    mma_tf32(acc[1][nt], c0, c1, c2, c3, bb.x, bb.y);
                }
            }

            // both n-half warps of the pair finished reading A before overwrite
            BAR_SYNC(8 + sp, 64);

            float* res = (float*)A;
            #pragma unroll
            for (int s = 0; s < 2; s++)
                #pragma unroll
                for (int nt = 0; nt < 8; nt++) {
                    int col = (h * 8 + nt) * 8 + 2 * t;
                    float b0 = sB[col], b1 = sB[col + 1];
                    int r0 = m0 + 16 * s + g;
                    *(float2*)(res + r0 * SA + col) =
                        make_float2(acc[s][nt][0] + b0, acc[s][nt][1] + b1);
                    *(float2*)(res + (r0 + 8) * SA + col) =
                        make_float2(acc[s][nt][2] + b0, acc[s][nt][3] + b1);
                }
            BAR_ARRIVE(1 + (v & 1), NT);                // FULL_v

            if (v >= 1 && v + 1 < VV) {
                BAR_SYNC(3 + ((v - 1) & 1), NT);        // FREE_{v-1}
                if (warp == 0)
                    issue_bulk_gather(t6 + (size_t)var_idx[b * VV + v + 1] * N6n * FF, sIdx,
                                      aB0 + ((v + 1) & 1) * TP * SA * 4,
                                      mb0 + ((v + 1) & 1) * 8, lane);
            }
        }
    } else {
        // ================= INTERP group (threads 256..511) =================
        const int itid = tid - 256;
        const int q    = warp - 8;
        const int pc4  = (p0 >> 4) + q;

        if (itid < 56) {
            int pp = itid / 7, nn = itid - pp * 7;
            sN4[itid] = nh4[((size_t)(b * P4p) + (p0 >> 4) + pp) * NHh + nn];
        }
        if (itid < 224) {
            int pp = itid / 7, nn = itid - pp * 7;
            sN5[itid] = nh5[((size_t)(b * P5p) + (p0 >> 2) + pp) * NHh + nn];
        }

        // per-lane weights -> packed per-warp smem table (v-invariant)
        float* wt = wtab + q * 512;
        {
            float w[NHh];
            const float* rdp; const float* mkp;
            if (lane < 16) {
                rdp = rd4 + ((size_t)(b * P4p + pc4) * 16 + lane) * NHh;
                mkp = m4  +  (size_t)(b * P4p + pc4) * NHh;
            } else {
                int g5 = lane - 16, s5 = g5 >> 2, o5 = g5 & 3;
                int pc5 = pc4 * 4 + s5;
                rdp = rd5 + ((size_t)(b * P5p + pc5) * 4 + o5) * NHh;
                mkp = m5  +  (size_t)(b * P5p + pc5) * NHh;
            }
            float ss = 0.f;
            #pragma unroll
            for (int n = 0; n < NHh; n++) {
                float x  = rdp[n] + mkp[n] * 1e10f;
                float wi = 1.0f / (1e-20f + x);
                w[n] = wi; ss += wi;
            }
            float inv = 1.0f / ss;
            #pragma unroll
            for (int n = 0; n < NHh; n++) w[n] *= inv;

            const int o = lane & 15;
            float2* dst = (float2*)(wt + o * 32) + (lane < 16 ? 0 : 1);
            #pragma unroll
            for (int n = 0; n < NHh; n++)
                dst[n * 2] = make_float2(w[n], w[n]);
        }
        __syncwarp();
        BAR_SYNC(7, 256);                               // sN4/sN5/wtab ready

        const ulonglong2* wt2 = (const ulonglong2*)wt;  // [o16*8 + n]

        for (int v = 0; v < VV; v++) {
            const int tv = var_idx[b * VV + v];
            const ulonglong2* tb4 = (const ulonglong2*)(t4 + (size_t)tv * N4n * FF);
            const ulonglong2* tb5 = (const ulonglong2*)(t5 + (size_t)tv * N5n * FF);
            const float* res = (const float*)(sA + (v & 1) * TP * SA);
            float* op = out + ((size_t)(b * VV + v) * PFp + p0 + q * 16) * EE;

            ulonglong2 f4[NHh], fA[NHh], fB[NHh];
            #pragma unroll
            for (int n = 0; n < NHh; n++)
                f4[n] = tb4[(size_t)sN4[q * 7 + n] * 32 + lane];
            #pragma unroll
            for (int n = 0; n < NHh; n++)
                fA[n] = tb5[(size_t)sN5[(q * 4 + 0) * 7 + n] * 32 + lane];

            BAR_SYNC(1 + (v & 1), NT);                  // FULL_v

            auto doS5 = [&](int s5, const ulonglong2* f5) {
                #pragma unroll
                for (int o5 = 0; o5 < 4; o5++) {
                    const int o16 = s5 * 4 + o5;
                    ulonglong2 a = *(const ulonglong2*)(res + (q * 16 + o16) * SA + 4 * lane);
                    u64 p0a = 0, p1a = 0;
                    #pragma unroll
                    for (int n = 0; n < NHh; n++) {
                        ulonglong2 wv = wt2[o16 * 8 + n];   // (w4w4, w5w5)
                        a.x = fma2(wv.x, f4[n].x, a.x);
                        a.y = fma2(wv.x, f4[n].y, a.y);
                        p0a = fma2(wv.y, f5[n].x, p0a);
                        p1a = fma2(wv.y, f5[n].y, p1a);
                    }
                    a.x = add2(a.x, p0a);
                    a.y = add2(a.y, p1a);
                    *(ulonglong2*)(op + (size_t)o16 * EE + 4 * lane) = a;
                }
            };

            #pragma unroll
            for (int n = 0; n < NHh; n++)
                fB[n] = tb5[(size_t)sN5[(q * 4 + 1) * 7 + n] * 32 + lane];
            doS5(0, fA);
            #pragma unroll
            for (int n = 0; n < NHh; n++)
                fA[n] = tb5[(size_t)sN5[(q * 4 + 2) * 7 + n] * 32 + lane];
            doS5(1, fB);
            #pragma unroll
            for (int n = 0; n < NHh; n++)
                fB[n] = tb5[(size_t)sN5[(q * 4 + 3) * 7 + n] * 32 + lane];
            doS5(2, fA);
            doS5(3, fB);

            BAR_ARRIVE(3 + (v & 1), NT);                // FREE_v
        }
    }
}

// ===================== launch =====================
extern "C" void kernel_launch(void* const* d_in, const int* in_sizes, int n_in,
                              void* d_out, int out_size)
{
    const float* table6  = (const float*)d_in[0];
    const float* table5  = (const float*)d_in[1];
    const float* table4  = (const float*)d_in[2];
    const float* W       = (const float*)d_in[3];
    const float* bias    = (const float*)d_in[4];
    const float* rd5     = (const float*)d_in[5];
    const float* rd4     = (const float*)d_in[6];
    const float* m5      = (const float*)d_in[7];
    const float* m4      = (const float*)d_in[8];
    const int*   var_idx = (const int*)d_in[9];
    const int*   idx6    = (const int*)d_in[10];
    const int*   nh5     = (const int*)d_in[11];
    const int*   nh4     = (const int*)d_in[12];
    float* out = (float*)d_out;

    // 16384 + 33792 + 128 + 128 + 56 + 224 + 8 + 4096 words = 219,264 B
    const int smem = (16384 + 2 * TP * SA + EE + TP + 56 + 224 + 8 + 4096) * 4;
    cudaFuncSetAttribute(fused_kernel, cudaFuncAttributeMaxDynamicSharedMemorySize, smem);

    dim3 grid(PFp / TP, BB);   // 512 CTAs
    fused_kernel<<<grid, NT, smem>>>(table6, table5, table4, W, bias,
                                     rd5, rd4, m5, m4,
                                     var_idx, idx6, nh5, nh4, out);
}

// round 8
// speedup vs baseline: 1.6320x; 1.0896x over previous
#include <cuda_runtime.h>
#include <cstdint>
#include <cstddef>

// ---------------- problem constants ----------------
#define FF   128
#define EE   128
#define VV   4
#define BB   2
#define NHh  7
#define PFp  32768
#define P5p  8192
#define P4p  2048
#define N6n  196608
#define N5n  49152
#define N4n  12288
#define TP   128
#define SA   132
#define NT   512

#define BAR_SYNC(id, cnt)   asm volatile("bar.sync %0, %1;\n"   :: "r"(id), "r"(cnt) : "memory")
#define BAR_ARRIVE(id, cnt) asm volatile("bar.arrive %0, %1;\n" :: "r"(id), "r"(cnt) : "memory")

typedef unsigned long long u64;

__device__ __forceinline__ unsigned f2tf32(float x) {
    unsigned y;
    asm("cvt.rna.tf32.f32 %0, %1;" : "=r"(y) : "f"(x));
    return y;
}

__device__ __forceinline__ u64 fma2(u64 a, u64 b, u64 c) {
    u64 d;
    asm("fma.rn.f32x2 %0, %1, %2, %3;" : "=l"(d) : "l"(a), "l"(b), "l"(c));
    return d;
}
__device__ __forceinline__ u64 add2(u64 a, u64 b) {
    u64 d;
    asm("add.rn.f32x2 %0, %1, %2;" : "=l"(d) : "l"(a), "l"(b));
    return d;
}

__device__ __forceinline__ void mma_tf32(float c[4],
                                         unsigned a0, unsigned a1, unsigned a2, unsigned a3,
                                         unsigned b0, unsigned b1) {
    asm volatile(
        "mma.sync.aligned.m16n8k8.row.col.f32.tf32.tf32.f32 "
        "{%0,%1,%2,%3}, {%4,%5,%6,%7}, {%8,%9}, {%0,%1,%2,%3};\n"
        : "+f"(c[0]), "+f"(c[1]), "+f"(c[2]), "+f"(c[3])
        : "r"(a0), "r"(a1), "r"(a2), "r"(a3), "r"(b0), "r"(b1));
}

__device__ __forceinline__ void cp16(unsigned dst, const void* src) {
    asm volatile("cp.async.cg.shared.global [%0], [%1], 16;\n" :: "r"(dst), "l"(src) : "memory");
}

__device__ __forceinline__ void issue_gather(const float* tb, const int* sIdx,
                                             unsigned aBase, int mtid) {
    #pragma unroll
    for (int j = 0; j < 16; j++) {
        int c = mtid + j * 256;
        int r = c >> 5, s = c & 31;
        cp16(aBase + (unsigned)(r * SA + s * 4) * 4u,
             tb + (size_t)sIdx[r] * FF + s * 4);
    }
    asm volatile("cp.async.commit_group;\n" ::: "memory");
}

// ===================== fused, warp-specialized =====================
// warps 0-7:  cp.async gather table6 + tf32 mma -> res in smem
// warps 8-15: e5/e4 interpolation (3-buffer rotating prefetch), write out
__global__ __launch_bounds__(NT, 1)
void fused_kernel(const float* __restrict__ t6, const float* __restrict__ t5,
                  const float* __restrict__ t4, const float* __restrict__ W,
                  const float* __restrict__ bias,
                  const float* __restrict__ rd5, const float* __restrict__ rd4,
                  const float* __restrict__ m5,  const float* __restrict__ m4,
                  const int* __restrict__ var_idx, const int* __restrict__ idx6,
                  const int* __restrict__ nh5, const int* __restrict__ nh4,
                  float* __restrict__ out)
{
    extern __shared__ unsigned sm[];
    unsigned* sWf  = sm;                               // 16384 words
    unsigned* sA   = sm + 16384;                       // 2 x [128][SA]
    float*    sB   = (float*)(sm + 16384 + 2 * TP * SA);
    int*      sIdx = (int*)(sB + EE);                  // [128]
    int*      sN4  = sIdx + TP;                        // [56]
    int*      sN5  = sN4 + 56;                         // [224]
    float*    wtab = (float*)(sN5 + 224);              // 8 pc4 x [16][8] float4

    const int b    = blockIdx.y;
    const int p0   = blockIdx.x * TP;
    const int tid  = threadIdx.x;
    const int warp = tid >> 5, lane = tid & 31;

    if (warp < 8) {
        // ================= MMA group (threads 0..255) =================
        const int mtid = tid;
        const int g = lane >> 2, t = lane & 3;
        const int m0 = warp * 16;

        if (mtid < TP) sIdx[mtid] = idx6[b * PFp + p0 + mtid];
        if (mtid < EE) sB[mtid]   = bias[mtid];
        BAR_SYNC(5, 256);

        issue_gather(t6 + (size_t)var_idx[b * VV + 0] * N6n * FF, sIdx,
                     (unsigned)__cvta_generic_to_shared(sA), mtid);
        issue_gather(t6 + (size_t)var_idx[b * VV + 1] * N6n * FF, sIdx,
                     (unsigned)__cvta_generic_to_shared(sA + TP * SA), mtid);

        // W in mma-fragment order (tf32, rna)
        for (int fi = mtid; fi < 8192; fi += 256) {
            int kt = fi >> 9, nt = (fi >> 5) & 15, ln = fi & 31;
            int gg = ln >> 2, tt = ln & 3;
            int k0 = kt * 8 + tt, n = nt * 8 + gg;
            sWf[fi * 2 + 0] = f2tf32(W[(size_t)k0 * EE + n]);
            sWf[fi * 2 + 1] = f2tf32(W[(size_t)(k0 + 4) * EE + n]);
        }

        for (int v = 0; v < VV; v++) {
            if (v == 0) { asm volatile("cp.async.wait_group 1;\n" ::: "memory"); }
            else        { asm volatile("cp.async.wait_group 0;\n" ::: "memory"); }
            BAR_SYNC(5, 256);

            const unsigned* A = sA + (v & 1) * TP * SA;
            float acc[16][4];
            #pragma unroll
            for (int nt = 0; nt < 16; nt++) {
                acc[nt][0] = 0.f; acc[nt][1] = 0.f; acc[nt][2] = 0.f; acc[nt][3] = 0.f;
            }
            #pragma unroll 2
            for (int kt = 0; kt < 16; kt++) {
                const int kb = kt * 8;
                unsigned a0 = A[(m0 + g    ) * SA + kb + t];
                unsigned a1 = A[(m0 + g + 8) * SA + kb + t];
                unsigned a2 = A[(m0 + g    ) * SA + kb + t + 4];
                unsigned a3 = A[(m0 + g + 8) * SA + kb + t + 4];
                const uint2* wrow = (const uint2*)sWf + kt * 512 + lane;
                #pragma unroll
                for (int nt = 0; nt < 16; nt++) {
                    uint2 bb = wrow[nt * 32];
                    mma_tf32(acc[nt], a0, a1, a2, a3, bb.x, bb.y);
                }
            }

            float* res = (float*)A;
            #pragma unroll
            for (int nt = 0; nt < 16; nt++) {
                int col = nt * 8 + 2 * t;
                float b0 = sB[col], b1 = sB[col + 1];
                *(float2*)(res + (m0 + g    ) * SA + col) =
                    make_float2(acc[nt][0] + b0, acc[nt][1] + b1);
                *(float2*)(res + (m0 + g + 8) * SA + col) =
                    make_float2(acc[nt][2] + b0, acc[nt][3] + b1);
            }
            BAR_ARRIVE(1 + (v & 1), NT);                // FULL_v

            if (v >= 1 && v + 1 < VV) {
                BAR_SYNC(3 + ((v - 1) & 1), NT);        // FREE_{v-1}
                issue_gather(t6 + (size_t)var_idx[b * VV + v + 1] * N6n * FF, sIdx,
                             (unsigned)__cvta_generic_to_shared(sA + ((v + 1) & 1) * TP * SA),
                             mtid);
            }
        }
    } else {
        // ================= INTERP group (threads 256..511) =================
        const int itid = tid - 256;
        const int q    = warp - 8;
        const int pc4  = (p0 >> 4) + q;

        if (itid < 56) {
            int pp = itid / 7, nn = itid - pp * 7;
            sN4[itid] = nh4[((size_t)(b * P4p) + (p0 >> 4) + pp) * NHh + nn];
        }
        if (itid < 224) {
            int pp = itid / 7, nn = itid - pp * 7;
            sN5[itid] = nh5[((size_t)(b * P5p) + (p0 >> 2) + pp) * NHh + nn];
        }

        // per-lane weights -> packed per-warp smem table (v-invariant)
        float* wt = wtab + q * 512;
        {
            float w[NHh];
            const float* rdp; const float* mkp;
            if (lane < 16) {
                rdp = rd4 + ((size_t)(b * P4p + pc4) * 16 + lane) * NHh;
                mkp = m4  +  (size_t)(b * P4p + pc4) * NHh;
            } else {
                int g5 = lane - 16, s5 = g5 >> 2, o5 = g5 & 3;
                int pc5 = pc4 * 4 + s5;
                rdp = rd5 + ((size_t)(b * P5p + pc5) * 4 + o5) * NHh;
                mkp = m5  +  (size_t)(b * P5p + pc5) * NHh;
            }
            float ss = 0.f;
            #pragma unroll
            for (int n = 0; n < NHh; n++) {
                float x  = rdp[n] + mkp[n] * 1e10f;
                float wi = 1.0f / (1e-20f + x);
                w[n] = wi; ss += wi;
            }
            float inv = 1.0f / ss;
            #pragma unroll
            for (int n = 0; n < NHh; n++) w[n] *= inv;

            const int o = lane & 15;
            float2* dst = (float2*)(wt + o * 32) + (lane < 16 ? 0 : 1);
            #pragma unroll
            for (int n = 0; n < NHh; n++)
                dst[n * 2] = make_float2(w[n], w[n]);
        }
        __syncwarp();
        BAR_SYNC(7, 256);                               // sN4/sN5/wtab ready

        const ulonglong2* wt2 = (const ulonglong2*)wt;  // [o16*8 + n]

        // 3 rotating row buffers; buf[v%3] holds f4 (e4 rows) during iter v.
        ulonglong2 buf[3][NHh];

        // preload f4 rows for v=0
        {
            const ulonglong2* tb4 =
                (const ulonglong2*)(t4 + (size_t)var_idx[b * VV + 0] * N4n * FF);
            #pragma unroll
            for (int n = 0; n < NHh; n++)
                buf[0][n] = tb4[(size_t)sN4[q * 7 + n] * 32 + lane];
        }

        #pragma unroll
        for (int v = 0; v < VV; v++) {
            const int fx = v % 3, sy = (v + 1) % 3, sz = (v + 2) % 3;
            const int tv = var_idx[b * VV + v];
            const ulonglong2* tb5 = (const ulonglong2*)(t5 + (size_t)tv * N5n * FF);
            const float* res = (const float*)(sA + (v & 1) * TP * SA);
            float* op = out + ((size_t)(b * VV + v) * PFp + p0 + q * 16) * EE;

            // prologue: s5=0 and s5=1 rows issued before FULL wait
            #pragma unroll
            for (int n = 0; n < NHh; n++)
                buf[sy][n] = tb5[(size_t)sN5[(q * 4 + 0) * 7 + n] * 32 + lane];
            #pragma unroll
            for (int n = 0; n < NHh; n++)
                buf[sz][n] = tb5[(size_t)sN5[(q * 4 + 1) * 7 + n] * 32 + lane];

            BAR_SYNC(1 + (v & 1), NT);                  // FULL_v

            auto doS5 = [&](int s5, const ulonglong2* f5) {
                const ulonglong2* f4 = buf[fx];
                #pragma unroll
                for (int o5 = 0; o5 < 4; o5++) {
                    const int o16 = s5 * 4 + o5;
                    ulonglong2 a = *(const ulonglong2*)(res + (q * 16 + o16) * SA + 4 * lane);
                    u64 p0a = 0, p1a = 0;
                    #pragma unroll
                    for (int n = 0; n < NHh; n++) {
                        ulonglong2 wv = wt2[o16 * 8 + n];   // (w4w4, w5w5)
                        a.x = fma2(wv.x, f4[n].x, a.x);
                        a.y = fma2(wv.x, f4[n].y, a.y);
                        p0a = fma2(wv.y, f5[n].x, p0a);
                        p1a = fma2(wv.y, f5[n].y, p1a);
                    }
                    a.x = add2(a.x, p0a);
                    a.y = add2(a.y, p1a);
                    *(ulonglong2*)(op + (size_t)o16 * EE + 4 * lane) = a;
                }
            };

            doS5(0, buf[sy]);
            #pragma unroll
            for (int n = 0; n < NHh; n++)               // s5=2 -> sy
                buf[sy][n] = tb5[(size_t)sN5[(q * 4 + 2) * 7 + n] * 32 + lane];
            doS5(1, buf[sz]);
            #pragma unroll
            for (int n = 0; n < NHh; n++)               // s5=3 -> sz
                buf[sz][n] = tb5[(size_t)sN5[(q * 4 + 3) * 7 + n] * 32 + lane];
            doS5(2, buf[sy]);
            if (v + 1 < VV) {
                // next v's f4 rows into sy = buf[(v+1)%3], hidden under doS5(3)
                const ulonglong2* tb4n =
                    (const ulonglong2*)(t4 + (size_t)var_idx[b * VV + v + 1] * N4n * FF);
                #pragma unroll
                for (int n = 0; n < NHh; n++)
                    buf[sy][n] = tb4n[(size_t)sN4[q * 7 + n] * 32 + lane];
            }
            doS5(3, buf[sz]);

            BAR_ARRIVE(3 + (v & 1), NT);                // FREE_v
        }
    }
}

// ===================== launch =====================
extern "C" void kernel_launch(void* const* d_in, const int* in_sizes, int n_in,
                              void* d_out, int out_size)
{
    const float* table6  = (const float*)d_in[0];
    const float* table5  = (const float*)d_in[1];
    const float* table4  = (const float*)d_in[2];
    const float* W       = (const float*)d_in[3];
    const float* bias    = (const float*)d_in[4];
    const float* rd5     = (const float*)d_in[5];
    const float* rd4     = (const float*)d_in[6];
    const float* m5      = (const float*)d_in[7];
    const float* m4      = (const float*)d_in[8];
    const int*   var_idx = (const int*)d_in[9];
    const int*   idx6    = (const int*)d_in[10];
    const int*   nh5     = (const int*)d_in[11];
    const int*   nh4     = (const int*)d_in[12];
    float* out = (float*)d_out;

    const int smem = (16384 + 2 * TP * SA + EE + TP + 56 + 224 + 4096) * 4;  // 219,232 B
    cudaFuncSetAttribute(fused_kernel, cudaFuncAttributeMaxDynamicSharedMemorySize, smem);

    dim3 grid(PFp / TP, BB);   // 512 CTAs
    fused_kernel<<<grid, NT, smem>>>(table6, table5, table4, W, bias,
                                     rd5, rd4, m5, m4,
                                     var_idx, idx6, nh5, nh4, out);
}